// round 3
// baseline (speedup 1.0000x reference)
#include <cuda_runtime.h>
#include <cstdint>

// Problem constants
#define BB   8
#define LL   512
#define DD   1024
#define SS   6144
#define MM   (BB * LL)     // 4096 GEMM rows
#define LP1  (LL + 1)      // 513 prefix rows

// Scratch (device globals: no allocation allowed)
__device__ float g_a[MM * DD];        // tf32-rounded h       (16 MB)
__device__ float g_w[DD * DD];        // tf32-rounded W       ( 4 MB)
__device__ float g_p[MM * DD];        // p = h @ W^T          (16 MB)
__device__ float g_g[BB * LP1 * DD];  // prefix sums of p     (16.8 MB)
__device__ int   g_is32;              // span_idx dtype flag

// ---------------------------------------------------------------------------
// helpers
// ---------------------------------------------------------------------------
__device__ __forceinline__ float tf32rna(float x) {
    uint32_t u;
    asm("cvt.rna.tf32.f32 %0, %1;" : "=r"(u) : "f"(x));
    return __uint_as_float(u);
}

__device__ __forceinline__ void mma_tf32(float c[4], const uint32_t a[4], const uint32_t b[2]) {
    asm volatile(
        "mma.sync.aligned.m16n8k8.row.col.f32.tf32.tf32.f32 "
        "{%0,%1,%2,%3}, {%4,%5,%6,%7}, {%8,%9}, {%0,%1,%2,%3};"
        : "+f"(c[0]), "+f"(c[1]), "+f"(c[2]), "+f"(c[3])
        : "r"(a[0]), "r"(a[1]), "r"(a[2]), "r"(a[3]),
          "r"(b[0]), "r"(b[1]));
}

__device__ __forceinline__ void cp16(uint32_t saddr, const void* gptr) {
    asm volatile("cp.async.cg.shared.global [%0], [%1], 16;\n"
                 :: "r"(saddr), "l"(gptr));
}
__device__ __forceinline__ void cp_commit() {
    asm volatile("cp.async.commit_group;\n");
}
__device__ __forceinline__ void cp_wait1() {
    asm volatile("cp.async.wait_group 1;\n");
}

// ---------------------------------------------------------------------------
// Kernel 0: tf32 pre-round (removes cvt from the GEMM hot loop)
// ---------------------------------------------------------------------------
__global__ void cvt_kernel(const float* __restrict__ src, float* __restrict__ dst, int n4)
{
    int i = blockIdx.x * blockDim.x + threadIdx.x;
    if (i >= n4) return;
    float4 v = ((const float4*)src)[i];
    v.x = tf32rna(v.x); v.y = tf32rna(v.y); v.z = tf32rna(v.z); v.w = tf32rna(v.w);
    ((float4*)dst)[i] = v;
}

// ---------------------------------------------------------------------------
// Kernel 1: p[m][n] = sum_d a[m][d] * w[n][d]  (tf32, cp.async 3-stage)
// Block tile 128x128x32, 256 threads (8 warps, 4x2), warp tile 32x64.
// Padded smem stride 36 floats -> conflict-free fragment LDS.
// ---------------------------------------------------------------------------
#define BM 128
#define BN 128
#define BK 32
#define BKF 36          // padded row stride in floats
#define STAGES 3
#define STAGE_A (BM * BKF)
#define STAGE_B (BN * BKF)

__global__ void __launch_bounds__(256, 1)
gemm_tf32_kernel(const float* __restrict__ A,   // g_a [4096,1024]
                 const float* __restrict__ Wm,  // g_w [1024,1024]
                 float* __restrict__ P)         // p   [4096,1024]
{
    extern __shared__ float smem[];
    float* Asm = smem;                            // STAGES * STAGE_A
    float* Bsm = smem + STAGES * STAGE_A;         // STAGES * STAGE_B

    const int tid  = threadIdx.x;
    const int warp = tid >> 5;
    const int lane = tid & 31;
    const int wm   = warp >> 1;   // 0..3
    const int wn   = warp & 1;    // 0..1
    const int m0   = blockIdx.x * BM;
    const int n0   = blockIdx.y * BN;

    const int lr = tid >> 3;          // 0..31
    const int lc = (tid & 7) * 4;     // float4 column within BK

    const float* Ag = A  + (size_t)(m0 + lr) * DD + lc;
    const float* Bg = Wm + (size_t)(n0 + lr) * DD + lc;

    const uint32_t sA = (uint32_t)__cvta_generic_to_shared(Asm);
    const uint32_t sB = (uint32_t)__cvta_generic_to_shared(Bsm);

    // issue one K-tile's loads into a stage
    auto issue = [&](int kt, int st) {
        const int ko = kt * BK;
        const uint32_t a0 = sA + (uint32_t)(st * STAGE_A + lr * BKF + lc) * 4;
        const uint32_t b0 = sB + (uint32_t)(st * STAGE_B + lr * BKF + lc) * 4;
        #pragma unroll
        for (int j = 0; j < 4; j++) {
            cp16(a0 + j * 32 * BKF * 4, Ag + (size_t)j * 32 * DD + ko);
            cp16(b0 + j * 32 * BKF * 4, Bg + (size_t)j * 32 * DD + ko);
        }
        cp_commit();
    };

    issue(0, 0);
    issue(1, 1);

    float acc[2][8][4];
    #pragma unroll
    for (int mt = 0; mt < 2; mt++)
        #pragma unroll
        for (int nt = 0; nt < 8; nt++)
            #pragma unroll
            for (int r = 0; r < 4; r++) acc[mt][nt][r] = 0.0f;

    const int NKT = DD / BK;  // 32
    for (int kt = 0; kt < NKT; kt++) {
        cp_wait1();            // stage kt's loads complete
        __syncthreads();       // also: everyone done computing stage kt-1

        if (kt + 2 < NKT) issue(kt + 2, (kt + 2) % STAGES);  // overlaps compute

        const float* As = Asm + (kt % STAGES) * STAGE_A;
        const float* Bs = Bsm + (kt % STAGES) * STAGE_B;

        #pragma unroll
        for (int ks = 0; ks < 4; ks++) {
            const int k0 = ks * 8 + (lane & 3);
            const int rA = wm * 32 + (lane >> 2);

            uint32_t af[2][4];
            #pragma unroll
            for (int mt = 0; mt < 2; mt++) {
                const int r = rA + mt * 16;
                af[mt][0] = __float_as_uint(As[r       * BKF + k0]);
                af[mt][1] = __float_as_uint(As[(r + 8) * BKF + k0]);
                af[mt][2] = __float_as_uint(As[r       * BKF + k0 + 4]);
                af[mt][3] = __float_as_uint(As[(r + 8) * BKF + k0 + 4]);
            }
            uint32_t bf[8][2];
            #pragma unroll
            for (int nt = 0; nt < 8; nt++) {
                const int n = wn * 64 + nt * 8 + (lane >> 2);
                bf[nt][0] = __float_as_uint(Bs[n * BKF + k0]);
                bf[nt][1] = __float_as_uint(Bs[n * BKF + k0 + 4]);
            }
            #pragma unroll
            for (int mt = 0; mt < 2; mt++)
                #pragma unroll
                for (int nt = 0; nt < 8; nt++)
                    mma_tf32(acc[mt][nt], af[mt], bf[nt]);
        }
        __syncthreads();
    }

    // epilogue: write p
    const int mrow = m0 + wm * 32 + (lane >> 2);
    const int ncol = n0 + wn * 64 + (lane & 3) * 2;
    #pragma unroll
    for (int mt = 0; mt < 2; mt++) {
        #pragma unroll
        for (int nt = 0; nt < 8; nt++) {
            const int r = mrow + mt * 16;
            const int c = ncol + nt * 8;
            *(float2*)(&P[(size_t)r       * DD + c]) = make_float2(acc[mt][nt][0], acc[mt][nt][1]);
            *(float2*)(&P[(size_t)(r + 8) * DD + c]) = make_float2(acc[mt][nt][2], acc[mt][nt][3]);
        }
    }
}

// ---------------------------------------------------------------------------
// Kernel 2: exclusive prefix sum over t of p, per (batch, feature).
// One thread per (b, e): 8192 threads. Also detects span_idx dtype.
// ---------------------------------------------------------------------------
__global__ void prefix_kernel(const float* __restrict__ P,
                              float* __restrict__ G,
                              const int* __restrict__ idx_words)
{
    if (blockIdx.x == 0 && threadIdx.x == 0) {
        // int64: odd 32-bit words are the zero high halves of values < 512.
        // int32: odd words are 'end' values -- 64 zeros is impossible.
        int any = 0;
        #pragma unroll
        for (int j = 0; j < 64; j++) any |= idx_words[2 * j + 1];
        g_is32 = (any != 0) ? 1 : 0;
    }

    const int gidx = blockIdx.x * blockDim.x + threadIdx.x;  // 0..8191
    const int b = gidx >> 10;
    const int e = gidx & (DD - 1);

    const float* p = P + (size_t)b * LL * DD + e;
    float*       g = G + (size_t)b * LP1 * DD + e;

    float c = 0.0f;
    g[0] = 0.0f;
    for (int t = 0; t < LL; t += 32) {
        float v[32];
        #pragma unroll
        for (int j = 0; j < 32; j++) v[j] = p[(size_t)(t + j) * DD];
        #pragma unroll
        for (int j = 0; j < 32; j++) {
            c += v[j];
            g[(size_t)(t + j + 1) * DD] = c;
        }
    }
}

// ---------------------------------------------------------------------------
// Kernel 3: epilogue. One block (256 thr) per span; each thread one float4.
// out[span][d] = relu((g[b][e+1][d] - g[b][s][d]) * inv_cnt + bias[d])
// Streaming (evict-first) output stores protect the L2-resident G table.
// ---------------------------------------------------------------------------
__global__ void __launch_bounds__(256)
epilogue_kernel(const int* __restrict__ idx_words,
                const float* __restrict__ G,
                const float* __restrict__ bias,
                float* __restrict__ out)
{
    const int span = blockIdx.x;          // 0 .. B*S-1
    const int b    = span / SS;

    int w0, w1;
    if (g_is32) {
        w0 = idx_words[2 * span];
        w1 = idx_words[2 * span + 1];
    } else {
        w0 = idx_words[4 * span];
        w1 = idx_words[4 * span + 2];
    }
    int s0 = min(max(w0, 0), LL - 1);
    int e0 = min(max(w1, 0), LL - 1);
    const bool  valid = (s0 <= e0);
    const float inv   = valid ? (1.0f / (float)(e0 - s0 + 1)) : 0.0f;

    const float* gs = G + ((size_t)b * LP1 + s0)     * DD;
    const float* ge = G + ((size_t)b * LP1 + e0 + 1) * DD;

    const int d = threadIdx.x * 4;
    float4 a  = *(const float4*)(ge + d);
    float4 c  = *(const float4*)(gs + d);
    float4 bb = *(const float4*)(bias + d);

    float4 o;
    o.x = fmaxf(fmaf(a.x - c.x, inv, bb.x), 0.0f);
    o.y = fmaxf(fmaf(a.y - c.y, inv, bb.y), 0.0f);
    o.z = fmaxf(fmaf(a.z - c.z, inv, bb.z), 0.0f);
    o.w = fmaxf(fmaf(a.w - c.w, inv, bb.w), 0.0f);

    __stcs((float4*)(out + (size_t)span * DD + d), o);
}

// ---------------------------------------------------------------------------
// launch
// ---------------------------------------------------------------------------
extern "C" void kernel_launch(void* const* d_in, const int* in_sizes, int n_in,
                              void* d_out, int out_size)
{
    // Match inputs by element count:
    //   h: 4,194,304   span_idx: 98,304   W: 1,048,576   b: 1,024
    const float* h   = nullptr;
    const void*  idx = nullptr;
    const float* W   = nullptr;
    const float* bia = nullptr;
    for (int i = 0; i < n_in; i++) {
        switch (in_sizes[i]) {
            case BB * LL * DD:   h   = (const float*)d_in[i]; break;
            case BB * SS * 2:    idx = d_in[i];               break;
            case DD * DD:        W   = (const float*)d_in[i]; break;
            case DD:             bia = (const float*)d_in[i]; break;
            default: break;
        }
    }

    float *a_s, *w_s, *p_s, *g_s;
    cudaGetSymbolAddress((void**)&a_s, g_a);
    cudaGetSymbolAddress((void**)&w_s, g_w);
    cudaGetSymbolAddress((void**)&p_s, g_p);
    cudaGetSymbolAddress((void**)&g_s, g_g);

    // 0) tf32 pre-round
    cvt_kernel<<<(MM * DD / 4 + 255) / 256, 256>>>(h, a_s, MM * DD / 4);
    cvt_kernel<<<(DD * DD / 4 + 255) / 256, 256>>>(W, w_s, DD * DD / 4);

    // 1) GEMM (108 KB dynamic smem)
    const int smem_bytes = STAGES * (STAGE_A + STAGE_B) * 4;
    cudaFuncSetAttribute(gemm_tf32_kernel,
                         cudaFuncAttributeMaxDynamicSharedMemorySize, smem_bytes);
    dim3 gemm_grid(MM / BM, DD / BN);  // 32 x 8
    gemm_tf32_kernel<<<gemm_grid, 256, smem_bytes>>>(a_s, w_s, p_s);

    // 2) prefix sums
    prefix_kernel<<<(BB * DD) / 64, 64>>>(p_s, g_s, (const int*)idx);

    // 3) epilogue
    epilogue_kernel<<<BB * SS, 256>>>((const int*)idx, g_s, bia, (float*)d_out);
}

// round 4
// speedup vs baseline: 1.1598x; 1.1598x over previous
#include <cuda_runtime.h>
#include <cstdint>

// Problem constants
#define BB   8
#define LL   512
#define DD   1024
#define SS   6144
#define MM   (BB * LL)     // 4096 GEMM rows
#define LP1  (LL + 1)      // 513 prefix rows
#define NT   8             // prefix tiles along t
#define TW   (LL / NT)     // 64 timesteps per tile

// Scratch (device globals: no allocation allowed)
__device__ float g_p[MM * DD];          // p = h @ W^T          (16 MB)
__device__ float g_g[BB * LP1 * DD];    // prefix sums of p     (16.8 MB)
__device__ float g_part[BB * NT * DD];  // per-tile partial sums (256 KB)
__device__ int   g_is32;                // span_idx dtype flag

// ---------------------------------------------------------------------------
// helpers
// ---------------------------------------------------------------------------
__device__ __forceinline__ float tf32rna(float x) {
    uint32_t u;
    asm("cvt.rna.tf32.f32 %0, %1;" : "=r"(u) : "f"(x));
    return __uint_as_float(u);
}

__device__ __forceinline__ void mma_tf32(float c[4], const uint32_t a[4], const uint32_t b[2]) {
    asm volatile(
        "mma.sync.aligned.m16n8k8.row.col.f32.tf32.tf32.f32 "
        "{%0,%1,%2,%3}, {%4,%5,%6,%7}, {%8,%9}, {%0,%1,%2,%3};"
        : "+f"(c[0]), "+f"(c[1]), "+f"(c[2]), "+f"(c[3])
        : "r"(a[0]), "r"(a[1]), "r"(a[2]), "r"(a[3]),
          "r"(b[0]), "r"(b[1]));
}

// ---------------------------------------------------------------------------
// Kernel 1: p[m][n] = sum_d h[m][d] * W[n][d]   (tf32 tensor-core GEMM)
// R2 version (known-good, 65.6us): 128x128x32 tile, 256 threads, register-
// staged prefetch, cvt.rna at STS time, KPAD=36 conflict-free.
// ---------------------------------------------------------------------------
#define BM 128
#define BN 128
#define BK 32
#define KPAD 36

__global__ void __launch_bounds__(256)
gemm_tf32_kernel(const float* __restrict__ A,   // h  [4096,1024]
                 const float* __restrict__ Wm,  // W  [1024,1024]
                 float* __restrict__ P)         // p  [4096,1024]
{
    __shared__ float As[BM * KPAD];
    __shared__ float Bs[BN * KPAD];

    const int tid  = threadIdx.x;
    const int warp = tid >> 5;
    const int lane = tid & 31;
    const int wm   = warp >> 1;   // 0..3
    const int wn   = warp & 1;    // 0..1
    const int m0   = blockIdx.x * BM;
    const int n0   = blockIdx.y * BN;

    const int lr = tid >> 3;
    const int lc = (tid & 7) * 4;

    const float* Ag = A  + (size_t)(m0 + lr) * DD + lc;
    const float* Bg = Wm + (size_t)(n0 + lr) * DD + lc;

    float acc[2][8][4];
    #pragma unroll
    for (int mt = 0; mt < 2; mt++)
        #pragma unroll
        for (int nt = 0; nt < 8; nt++)
            #pragma unroll
            for (int r = 0; r < 4; r++) acc[mt][nt][r] = 0.0f;

    float4 ra[4], rb[4];
    #pragma unroll
    for (int j = 0; j < 4; j++) {
        ra[j] = *(const float4*)(Ag + (size_t)j * 32 * DD);
        rb[j] = *(const float4*)(Bg + (size_t)j * 32 * DD);
    }

    const int NKT = DD / BK;  // 32
    for (int kt = 0; kt < NKT; kt++) {
        #pragma unroll
        for (int j = 0; j < 4; j++) {
            float4 a = ra[j], b = rb[j];
            a.x = tf32rna(a.x); a.y = tf32rna(a.y); a.z = tf32rna(a.z); a.w = tf32rna(a.w);
            b.x = tf32rna(b.x); b.y = tf32rna(b.y); b.z = tf32rna(b.z); b.w = tf32rna(b.w);
            *(float4*)(&As[(lr + j * 32) * KPAD + lc]) = a;
            *(float4*)(&Bs[(lr + j * 32) * KPAD + lc]) = b;
        }
        __syncthreads();

        if (kt + 1 < NKT) {
            const int ko = (kt + 1) * BK;
            #pragma unroll
            for (int j = 0; j < 4; j++) {
                ra[j] = *(const float4*)(Ag + (size_t)j * 32 * DD + ko);
                rb[j] = *(const float4*)(Bg + (size_t)j * 32 * DD + ko);
            }
        }

        #pragma unroll
        for (int ks = 0; ks < 4; ks++) {
            const int k0 = ks * 8 + (lane & 3);
            const int rA = wm * 32 + (lane >> 2);

            uint32_t af[2][4];
            #pragma unroll
            for (int mt = 0; mt < 2; mt++) {
                const int r = rA + mt * 16;
                af[mt][0] = __float_as_uint(As[r       * KPAD + k0]);
                af[mt][1] = __float_as_uint(As[(r + 8) * KPAD + k0]);
                af[mt][2] = __float_as_uint(As[r       * KPAD + k0 + 4]);
                af[mt][3] = __float_as_uint(As[(r + 8) * KPAD + k0 + 4]);
            }
            uint32_t bf[8][2];
            #pragma unroll
            for (int nt = 0; nt < 8; nt++) {
                const int n = wn * 64 + nt * 8 + (lane >> 2);
                bf[nt][0] = __float_as_uint(Bs[n * KPAD + k0]);
                bf[nt][1] = __float_as_uint(Bs[n * KPAD + k0 + 4]);
            }
            #pragma unroll
            for (int mt = 0; mt < 2; mt++)
                #pragma unroll
                for (int nt = 0; nt < 8; nt++)
                    mma_tf32(acc[mt][nt], af[mt], bf[nt]);
        }
        __syncthreads();
    }

    const int mrow = m0 + wm * 32 + (lane >> 2);
    const int ncol = n0 + wn * 64 + (lane & 3) * 2;
    #pragma unroll
    for (int mt = 0; mt < 2; mt++) {
        #pragma unroll
        for (int nt = 0; nt < 8; nt++) {
            const int r = mrow + mt * 16;
            const int c = ncol + nt * 8;
            *(float2*)(&P[(size_t)r       * DD + c]) = make_float2(acc[mt][nt][0], acc[mt][nt][1]);
            *(float2*)(&P[(size_t)(r + 8) * DD + c]) = make_float2(acc[mt][nt][2], acc[mt][nt][3]);
        }
    }
}

// ---------------------------------------------------------------------------
// Kernel 2a: per-tile partial sums.
// thread -> (b, tile, e): part[b][tile][e] = sum_{j<TW} p[b][tile*TW+j][e]
// 65536 threads (8x more parallelism than the old single-pass scan).
// Also detects span_idx dtype.
// ---------------------------------------------------------------------------
__global__ void __launch_bounds__(256)
prefix_partial_kernel(const float* __restrict__ P,
                      float* __restrict__ part,
                      const int* __restrict__ idx_words)
{
    if (blockIdx.x == 0 && threadIdx.x == 0) {
        // int64: odd 32-bit words are the zero high halves of values < 512.
        // int32: odd words are 'end' values -- 64 zeros is impossible.
        int any = 0;
        #pragma unroll
        for (int j = 0; j < 64; j++) any |= idx_words[2 * j + 1];
        g_is32 = (any != 0) ? 1 : 0;
    }

    const int gidx = blockIdx.x * blockDim.x + threadIdx.x;  // 0..65535
    const int e    = gidx & (DD - 1);
    const int tile = (gidx >> 10) & (NT - 1);
    const int b    = gidx >> 13;

    const float* p = P + ((size_t)b * LL + tile * TW) * DD + e;

    float s = 0.0f;
    #pragma unroll
    for (int j = 0; j < TW; j++) s += p[(size_t)j * DD];

    part[((size_t)b * NT + tile) * DD + e] = s;
}

// ---------------------------------------------------------------------------
// Kernel 2b: scan within tile using tile offsets.
// thread -> (b, tile, e): offset = sum of part[b][t'][e] for t' < tile,
// then running sum over the tile's TW values, writing g[b][t+1][e].
// tile 0 also writes g[b][0][e] = 0.
// ---------------------------------------------------------------------------
__global__ void __launch_bounds__(256)
prefix_scan_kernel(const float* __restrict__ P,
                   const float* __restrict__ part,
                   float* __restrict__ G)
{
    const int gidx = blockIdx.x * blockDim.x + threadIdx.x;  // 0..65535
    const int e    = gidx & (DD - 1);
    const int tile = (gidx >> 10) & (NT - 1);
    const int b    = gidx >> 13;

    float c = 0.0f;
    for (int t = 0; t < tile; t++)
        c += part[((size_t)b * NT + t) * DD + e];

    const float* p = P + ((size_t)b * LL + tile * TW) * DD + e;
    float*       g = G + ((size_t)b * LP1 + tile * TW) * DD + e;

    if (tile == 0) g[0] = 0.0f;

    #pragma unroll 8
    for (int j = 0; j < TW; j++) {
        c += p[(size_t)j * DD];
        g[(size_t)(j + 1) * DD] = c;
    }
}

// ---------------------------------------------------------------------------
// Kernel 3: epilogue (R2 version). One block (256 thr) per span.
// out[span][d] = relu((g[b][e+1][d] - g[b][s][d]) * inv_cnt + bias[d])
// ---------------------------------------------------------------------------
__global__ void __launch_bounds__(256)
epilogue_kernel(const int* __restrict__ idx_words,
                const float* __restrict__ G,
                const float* __restrict__ bias,
                float* __restrict__ out)
{
    const int span = blockIdx.x;          // 0 .. B*S-1
    const int b    = span / SS;

    int w0, w1;
    if (g_is32) {
        w0 = idx_words[2 * span];
        w1 = idx_words[2 * span + 1];
    } else {
        w0 = idx_words[4 * span];
        w1 = idx_words[4 * span + 2];
    }
    int s0 = min(max(w0, 0), LL - 1);
    int e0 = min(max(w1, 0), LL - 1);
    const bool  valid = (s0 <= e0);
    const float inv   = valid ? (1.0f / (float)(e0 - s0 + 1)) : 0.0f;

    const float* gs = G + ((size_t)b * LP1 + s0)     * DD;
    const float* ge = G + ((size_t)b * LP1 + e0 + 1) * DD;

    const int d = threadIdx.x * 4;
    float4 a  = *(const float4*)(ge + d);
    float4 c  = *(const float4*)(gs + d);
    float4 bb = *(const float4*)(bias + d);

    float4 o;
    o.x = fmaxf(fmaf(a.x - c.x, inv, bb.x), 0.0f);
    o.y = fmaxf(fmaf(a.y - c.y, inv, bb.y), 0.0f);
    o.z = fmaxf(fmaf(a.z - c.z, inv, bb.z), 0.0f);
    o.w = fmaxf(fmaf(a.w - c.w, inv, bb.w), 0.0f);

    *(float4*)(out + (size_t)span * DD + d) = o;
}

// ---------------------------------------------------------------------------
// launch
// ---------------------------------------------------------------------------
extern "C" void kernel_launch(void* const* d_in, const int* in_sizes, int n_in,
                              void* d_out, int out_size)
{
    // Match inputs by element count:
    //   h: 4,194,304   span_idx: 98,304   W: 1,048,576   b: 1,024
    const float* h   = nullptr;
    const void*  idx = nullptr;
    const float* W   = nullptr;
    const float* bia = nullptr;
    for (int i = 0; i < n_in; i++) {
        switch (in_sizes[i]) {
            case BB * LL * DD:   h   = (const float*)d_in[i]; break;
            case BB * SS * 2:    idx = d_in[i];               break;
            case DD * DD:        W   = (const float*)d_in[i]; break;
            case DD:             bia = (const float*)d_in[i]; break;
            default: break;
        }
    }

    float *p_s, *g_s, *part_s;
    cudaGetSymbolAddress((void**)&p_s, g_p);
    cudaGetSymbolAddress((void**)&g_s, g_g);
    cudaGetSymbolAddress((void**)&part_s, g_part);

    dim3 gemm_grid(MM / BM, DD / BN);  // 32 x 8
    gemm_tf32_kernel<<<gemm_grid, 256>>>(h, W, p_s);

    const int nscan = BB * NT * DD;    // 65536
    prefix_partial_kernel<<<nscan / 256, 256>>>(p_s, part_s, (const int*)idx);
    prefix_scan_kernel<<<nscan / 256, 256>>>(p_s, part_s, g_s);

    epilogue_kernel<<<BB * SS, 256>>>((const int*)idx, g_s, bia, (float*)d_out);
}

// round 5
// speedup vs baseline: 1.1618x; 1.0017x over previous
#include <cuda_runtime.h>
#include <cstdint>

// Problem constants
#define BB   8
#define LL   512
#define DD   1024
#define SS   6144
#define NSPAN (BB * SS)    // 49152 spans
#define MM   (BB * LL)     // 4096 GEMM rows
#define LP1  (LL + 1)      // 513 prefix rows
#define NT   8             // prefix tiles along t
#define TW   (LL / NT)     // 64 timesteps per tile
#define NBUCK (BB * LL)    // 4096 (b, s0) buckets

// Scratch (device globals: no allocation allowed)
__device__ float g_p[MM * DD];          // p = h @ W^T          (16 MB)
__device__ float g_g[BB * LP1 * DD];    // prefix sums of p     (16.8 MB)
__device__ float g_part[BB * NT * DD];  // per-tile partial sums (256 KB)

__device__ int   g_hist[NBUCK];         // bucket histogram
__device__ int   g_bstart[NBUCK + 1];   // bucket offsets (excl scan)
__device__ int   g_cursor[NBUCK];       // scatter cursors
__device__ int   g_sorted_span[NSPAN];  // valid spans sorted by (b,s0)
__device__ int   g_sorted_ge[NSPAN];    // global G row of end+1
__device__ float g_sorted_inv[NSPAN];   // 1/count
__device__ int   g_invlist[NSPAN];      // invalid span ids
__device__ int   g_invcount;

// ---------------------------------------------------------------------------
// helpers
// ---------------------------------------------------------------------------
__device__ __forceinline__ float tf32rna(float x) {
    uint32_t u;
    asm("cvt.rna.tf32.f32 %0, %1;" : "=r"(u) : "f"(x));
    return __uint_as_float(u);
}

__device__ __forceinline__ void mma_tf32(float c[4], const uint32_t a[4], const uint32_t b[2]) {
    asm volatile(
        "mma.sync.aligned.m16n8k8.row.col.f32.tf32.tf32.f32 "
        "{%0,%1,%2,%3}, {%4,%5,%6,%7}, {%8,%9}, {%0,%1,%2,%3};"
        : "+f"(c[0]), "+f"(c[1]), "+f"(c[2]), "+f"(c[3])
        : "r"(a[0]), "r"(a[1]), "r"(a[2]), "r"(a[3]),
          "r"(b[0]), "r"(b[1]));
}

// decode one span's (s0, e0) robustly to idx dtype (is32 computed per block)
__device__ __forceinline__ void decode_span(const int* idx_words, int span, int is32,
                                            int& s0, int& e0) {
    int w0, w1;
    if (is32) {
        w0 = idx_words[2 * span];
        w1 = idx_words[2 * span + 1];
    } else {
        w0 = idx_words[4 * span];
        w1 = idx_words[4 * span + 2];
    }
    s0 = min(max(w0, 0), LL - 1);
    e0 = min(max(w1, 0), LL - 1);
}

__device__ __forceinline__ int detect_is32(const int* idx_words) {
    // int64: odd 32-bit words are the zero high halves of values < 512.
    // int32: odd words are 'end' values -- 64 zeros is impossible.
    int any = 0;
    #pragma unroll
    for (int j = 0; j < 64; j++) any |= idx_words[2 * j + 1];
    return (any != 0) ? 1 : 0;
}

// ---------------------------------------------------------------------------
// Kernel 1: GEMM (unchanged known-good R2/R4 version, 65.6us)
// ---------------------------------------------------------------------------
#define BM 128
#define BN 128
#define BK 32
#define KPAD 36

__global__ void __launch_bounds__(256)
gemm_tf32_kernel(const float* __restrict__ A,
                 const float* __restrict__ Wm,
                 float* __restrict__ P)
{
    __shared__ float As[BM * KPAD];
    __shared__ float Bs[BN * KPAD];

    const int tid  = threadIdx.x;
    const int warp = tid >> 5;
    const int lane = tid & 31;
    const int wm   = warp >> 1;
    const int wn   = warp & 1;
    const int m0   = blockIdx.x * BM;
    const int n0   = blockIdx.y * BN;

    const int lr = tid >> 3;
    const int lc = (tid & 7) * 4;

    const float* Ag = A  + (size_t)(m0 + lr) * DD + lc;
    const float* Bg = Wm + (size_t)(n0 + lr) * DD + lc;

    float acc[2][8][4];
    #pragma unroll
    for (int mt = 0; mt < 2; mt++)
        #pragma unroll
        for (int nt = 0; nt < 8; nt++)
            #pragma unroll
            for (int r = 0; r < 4; r++) acc[mt][nt][r] = 0.0f;

    float4 ra[4], rb[4];
    #pragma unroll
    for (int j = 0; j < 4; j++) {
        ra[j] = *(const float4*)(Ag + (size_t)j * 32 * DD);
        rb[j] = *(const float4*)(Bg + (size_t)j * 32 * DD);
    }

    const int NKT = DD / BK;
    for (int kt = 0; kt < NKT; kt++) {
        #pragma unroll
        for (int j = 0; j < 4; j++) {
            float4 a = ra[j], b = rb[j];
            a.x = tf32rna(a.x); a.y = tf32rna(a.y); a.z = tf32rna(a.z); a.w = tf32rna(a.w);
            b.x = tf32rna(b.x); b.y = tf32rna(b.y); b.z = tf32rna(b.z); b.w = tf32rna(b.w);
            *(float4*)(&As[(lr + j * 32) * KPAD + lc]) = a;
            *(float4*)(&Bs[(lr + j * 32) * KPAD + lc]) = b;
        }
        __syncthreads();

        if (kt + 1 < NKT) {
            const int ko = (kt + 1) * BK;
            #pragma unroll
            for (int j = 0; j < 4; j++) {
                ra[j] = *(const float4*)(Ag + (size_t)j * 32 * DD + ko);
                rb[j] = *(const float4*)(Bg + (size_t)j * 32 * DD + ko);
            }
        }

        #pragma unroll
        for (int ks = 0; ks < 4; ks++) {
            const int k0 = ks * 8 + (lane & 3);
            const int rA = wm * 32 + (lane >> 2);

            uint32_t af[2][4];
            #pragma unroll
            for (int mt = 0; mt < 2; mt++) {
                const int r = rA + mt * 16;
                af[mt][0] = __float_as_uint(As[r       * KPAD + k0]);
                af[mt][1] = __float_as_uint(As[(r + 8) * KPAD + k0]);
                af[mt][2] = __float_as_uint(As[r       * KPAD + k0 + 4]);
                af[mt][3] = __float_as_uint(As[(r + 8) * KPAD + k0 + 4]);
            }
            uint32_t bf[8][2];
            #pragma unroll
            for (int nt = 0; nt < 8; nt++) {
                const int n = wn * 64 + nt * 8 + (lane >> 2);
                bf[nt][0] = __float_as_uint(Bs[n * KPAD + k0]);
                bf[nt][1] = __float_as_uint(Bs[n * KPAD + k0 + 4]);
            }
            #pragma unroll
            for (int mt = 0; mt < 2; mt++)
                #pragma unroll
                for (int nt = 0; nt < 8; nt++)
                    mma_tf32(acc[mt][nt], af[mt], bf[nt]);
        }
        __syncthreads();
    }

    const int mrow = m0 + wm * 32 + (lane >> 2);
    const int ncol = n0 + wn * 64 + (lane & 3) * 2;
    #pragma unroll
    for (int mt = 0; mt < 2; mt++) {
        #pragma unroll
        for (int nt = 0; nt < 8; nt++) {
            const int r = mrow + mt * 16;
            const int c = ncol + nt * 8;
            *(float2*)(&P[(size_t)r       * DD + c]) = make_float2(acc[mt][nt][0], acc[mt][nt][1]);
            *(float2*)(&P[(size_t)(r + 8) * DD + c]) = make_float2(acc[mt][nt][2], acc[mt][nt][3]);
        }
    }
}

// ---------------------------------------------------------------------------
// Kernel 2a/2b: two-pass prefix sums (unchanged from R4, ~8us)
// ---------------------------------------------------------------------------
__global__ void __launch_bounds__(256)
prefix_partial_kernel(const float* __restrict__ P, float* __restrict__ part)
{
    const int gidx = blockIdx.x * blockDim.x + threadIdx.x;
    const int e    = gidx & (DD - 1);
    const int tile = (gidx >> 10) & (NT - 1);
    const int b    = gidx >> 13;

    const float* p = P + ((size_t)b * LL + tile * TW) * DD + e;
    float s = 0.0f;
    #pragma unroll
    for (int j = 0; j < TW; j++) s += p[(size_t)j * DD];
    part[((size_t)b * NT + tile) * DD + e] = s;
}

__global__ void __launch_bounds__(256)
prefix_scan_kernel(const float* __restrict__ P,
                   const float* __restrict__ part,
                   float* __restrict__ G)
{
    const int gidx = blockIdx.x * blockDim.x + threadIdx.x;
    const int e    = gidx & (DD - 1);
    const int tile = (gidx >> 10) & (NT - 1);
    const int b    = gidx >> 13;

    float c = 0.0f;
    for (int t = 0; t < tile; t++)
        c += part[((size_t)b * NT + t) * DD + e];

    const float* p = P + ((size_t)b * LL + tile * TW) * DD + e;
    float*       g = G + ((size_t)b * LP1 + tile * TW) * DD + e;

    if (tile == 0) g[0] = 0.0f;

    #pragma unroll 8
    for (int j = 0; j < TW; j++) {
        c += p[(size_t)j * DD];
        g[(size_t)(j + 1) * DD] = c;
    }
}

// ---------------------------------------------------------------------------
// Sort machinery
// ---------------------------------------------------------------------------
__global__ void init_kernel()
{
    const int i = blockIdx.x * blockDim.x + threadIdx.x;
    if (i < NBUCK) g_hist[i] = 0;
    if (i == 0)    g_invcount = 0;
}

// histogram valid spans by (b, s0); collect invalid spans into a list
__global__ void __launch_bounds__(256)
decode_kernel(const int* __restrict__ idx_words)
{
    __shared__ int s_is32;
    if (threadIdx.x == 0) s_is32 = detect_is32(idx_words);
    __syncthreads();

    const int span = blockIdx.x * blockDim.x + threadIdx.x;  // < NSPAN
    const int b    = span / SS;
    int s0, e0;
    decode_span(idx_words, span, s_is32, s0, e0);

    if (s0 <= e0) {
        atomicAdd(&g_hist[b * LL + s0], 1);
    } else {
        int p = atomicAdd(&g_invcount, 1);
        g_invlist[p] = span;
    }
}

// exclusive scan of 4096 bins; one block of 1024 threads, 4 bins each
__global__ void __launch_bounds__(1024)
binscan_kernel()
{
    __shared__ int sm[1024];
    const int tid = threadIdx.x;
    const int base = tid * 4;

    int v0 = g_hist[base], v1 = g_hist[base + 1],
        v2 = g_hist[base + 2], v3 = g_hist[base + 3];
    int s = v0 + v1 + v2 + v3;

    sm[tid] = s;
    __syncthreads();
    // Hillis-Steele inclusive scan
    #pragma unroll
    for (int d = 1; d < 1024; d <<= 1) {
        int t = (tid >= d) ? sm[tid - d] : 0;
        __syncthreads();
        sm[tid] += t;
        __syncthreads();
    }
    int off = sm[tid] - s;  // exclusive

    g_bstart[base] = off;  g_cursor[base] = off;  off += v0;
    g_bstart[base + 1] = off; g_cursor[base + 1] = off; off += v1;
    g_bstart[base + 2] = off; g_cursor[base + 2] = off; off += v2;
    g_bstart[base + 3] = off; g_cursor[base + 3] = off;
    if (tid == 1023) g_bstart[NBUCK] = sm[1023];
}

// scatter valid spans into sorted order
__global__ void __launch_bounds__(256)
scatter_kernel(const int* __restrict__ idx_words)
{
    __shared__ int s_is32;
    if (threadIdx.x == 0) s_is32 = detect_is32(idx_words);
    __syncthreads();

    const int span = blockIdx.x * blockDim.x + threadIdx.x;
    const int b    = span / SS;
    int s0, e0;
    decode_span(idx_words, span, s_is32, s0, e0);
    if (s0 > e0) return;

    const int pos = atomicAdd(&g_cursor[b * LL + s0], 1);
    g_sorted_span[pos] = span;
    g_sorted_ge[pos]   = b * LP1 + e0 + 1;
    g_sorted_inv[pos]  = 1.0f / (float)(e0 - s0 + 1);
}

// ---------------------------------------------------------------------------
// Epilogue A: valid spans, one block per (b,s0) bucket. gs row loaded once
// into registers; loop over the bucket's spans reading only the ge row.
// ---------------------------------------------------------------------------
__global__ void __launch_bounds__(256)
epi_valid_kernel(const float* __restrict__ G,
                 const float* __restrict__ bias,
                 float* __restrict__ out)
{
    const int k  = blockIdx.x;             // bucket = b*512 + s0
    const int lo = g_bstart[k];
    const int hi = g_bstart[k + 1];
    if (lo == hi) return;

    const int b  = k >> 9;
    const int s0 = k & (LL - 1);
    const int d  = threadIdx.x * 4;

    const float4 c  = *(const float4*)(G + ((size_t)b * LP1 + s0) * DD + d);
    const float4 bb = *(const float4*)(bias + d);

    for (int i = lo; i < hi; i++) {
        const int   orow  = g_sorted_span[i];
        const int   gerow = g_sorted_ge[i];
        const float inv   = g_sorted_inv[i];

        float4 a = *(const float4*)(G + (size_t)gerow * DD + d);
        float4 o;
        o.x = fmaxf(fmaf(a.x - c.x, inv, bb.x), 0.0f);
        o.y = fmaxf(fmaf(a.y - c.y, inv, bb.y), 0.0f);
        o.z = fmaxf(fmaf(a.z - c.z, inv, bb.z), 0.0f);
        o.w = fmaxf(fmaf(a.w - c.w, inv, bb.w), 0.0f);
        *(float4*)(out + (size_t)orow * DD + d) = o;
    }
}

// ---------------------------------------------------------------------------
// Epilogue B: invalid spans -> relu(bias) broadcast rows. Grid-stride.
// ---------------------------------------------------------------------------
__global__ void __launch_bounds__(256)
epi_invalid_kernel(const float* __restrict__ bias, float* __restrict__ out)
{
    const int d = threadIdx.x * 4;
    float4 bb = *(const float4*)(bias + d);
    float4 o;
    o.x = fmaxf(bb.x, 0.0f);
    o.y = fmaxf(bb.y, 0.0f);
    o.z = fmaxf(bb.z, 0.0f);
    o.w = fmaxf(bb.w, 0.0f);

    const int n = g_invcount;
    for (int i = blockIdx.x; i < n; i += gridDim.x) {
        const int row = g_invlist[i];
        *(float4*)(out + (size_t)row * DD + d) = o;
    }
}

// ---------------------------------------------------------------------------
// launch
// ---------------------------------------------------------------------------
extern "C" void kernel_launch(void* const* d_in, const int* in_sizes, int n_in,
                              void* d_out, int out_size)
{
    const float* h   = nullptr;
    const void*  idx = nullptr;
    const float* W   = nullptr;
    const float* bia = nullptr;
    for (int i = 0; i < n_in; i++) {
        switch (in_sizes[i]) {
            case BB * LL * DD:   h   = (const float*)d_in[i]; break;
            case BB * SS * 2:    idx = d_in[i];               break;
            case DD * DD:        W   = (const float*)d_in[i]; break;
            case DD:             bia = (const float*)d_in[i]; break;
            default: break;
        }
    }

    float *p_s, *g_s, *part_s;
    cudaGetSymbolAddress((void**)&p_s, g_p);
    cudaGetSymbolAddress((void**)&g_s, g_g);
    cudaGetSymbolAddress((void**)&part_s, g_part);

    // sort machinery (tiny; overlaps nothing, stream-serial)
    init_kernel<<<(NBUCK + 255) / 256, 256>>>();
    decode_kernel<<<NSPAN / 256, 256>>>((const int*)idx);
    binscan_kernel<<<1, 1024>>>();
    scatter_kernel<<<NSPAN / 256, 256>>>((const int*)idx);

    // main pipeline
    dim3 gemm_grid(MM / BM, DD / BN);
    gemm_tf32_kernel<<<gemm_grid, 256>>>(h, W, p_s);

    const int nscan = BB * NT * DD;
    prefix_partial_kernel<<<nscan / 256, 256>>>(p_s, part_s);
    prefix_scan_kernel<<<nscan / 256, 256>>>(p_s, part_s, g_s);

    epi_valid_kernel<<<NBUCK, 256>>>(g_s, bia, (float*)d_out);
    epi_invalid_kernel<<<2048, 256>>>(bia, (float*)d_out);
}